// round 5
// baseline (speedup 1.0000x reference)
#include <cuda_runtime.h>
#include <cstdint>

// AtomDistances: out[b,a,n] = mask ? || pos[nbr[b,a,n]] - pos[b,a] + cell_offsets[b,a,n,:] @ cell[b] || : 0
// B=16, A=4096, N=128 (derived from in_sizes).
//
// dtype contract (harness cast set is {float32,int32,bf16}):
//   neighbors     int64 -> int32   (confirmed: 8B-wide read IMA'd in R1)
//   neighbor_mask bool  -> int32   (confirmed: rel_err 0.894 == sqrt(0.8), the exact
//                                   signature of reading int32 bools as bytes)
//
// Streaming layout: each thread handles 4 consecutive neighbors:
//   neighbors    : 1 x int4    (16 B)
//   cell_offsets : 3 x float4  (48 B)
//   mask         : 1 x int4    (16 B)
//   out          : 1 x float4  (16 B)
// positions (786 KB) + cell stay L2-resident; gather latency hidden by occupancy.

__global__ void __launch_bounds__(256) atom_distances_kernel(
    const float* __restrict__ pos,    // (B, A, 3)
    const int*   __restrict__ nbr,    // (B, A, N) int32
    const float* __restrict__ cell,   // (B, 3, 3)
    const float* __restrict__ coff,   // (B, A, N, 3)
    const int*   __restrict__ mask,   // (B, A, N) int32 (0/1)
    float*       __restrict__ out,    // (B, A, N)
    int A, int N, long long n_groups) // n_groups = B*A*N/4
{
    long long g = (long long)blockIdx.x * blockDim.x + threadIdx.x;
    if (g >= n_groups) return;

    const int ng_per_atom = N >> 2;           // groups of 4 neighbors per atom
    int n4       = (int)(g % ng_per_atom);
    long long ba = g / ng_per_atom;           // b*A + a
    int b        = (int)(ba / A);

    long long base = ba * N + (long long)n4 * 4;   // element index of first of 4

    // --- front-batched wide streaming loads (MLP) ---
    int4 nb4 = *reinterpret_cast<const int4*>(nbr + base);

    const float4* co4 = reinterpret_cast<const float4*>(coff + base * 3);
    float4 q0 = co4[0];
    float4 q1 = co4[1];
    float4 q2 = co4[2];

    int4 m4 = *reinterpret_cast<const int4*>(mask + base);

    // central atom position (L2/L1 hit; shared by 32 threads)
    const float* pa = pos + ba * 3;
    float ax = __ldg(pa + 0), ay = __ldg(pa + 1), az = __ldg(pa + 2);

    // cell matrix for this batch (9 floats, L1-resident)
    const float* C = cell + (long long)b * 9;
    float c00 = __ldg(C+0), c01 = __ldg(C+1), c02 = __ldg(C+2);
    float c10 = __ldg(C+3), c11 = __ldg(C+4), c12 = __ldg(C+5);
    float c20 = __ldg(C+6), c21 = __ldg(C+7), c22 = __ldg(C+8);

    int ni[4] = { nb4.x, nb4.y, nb4.z, nb4.w };
#pragma unroll
    for (int i = 0; i < 4; i++) {              // defensive clamp: never OOB gather
        ni[i] = min(max(ni[i], 0), A - 1);
    }
    float cox[4] = { q0.x, q0.w, q1.z, q2.y };
    float coy[4] = { q0.y, q1.x, q1.w, q2.z };
    float coz[4] = { q0.z, q1.y, q2.x, q2.w };
    int   mm[4]  = { m4.x, m4.y, m4.z, m4.w };

    const float* pbase = pos + (long long)b * A * 3;

    float res[4];
#pragma unroll
    for (int i = 0; i < 4; i++) {
        const float* pn = pbase + (long long)ni[i] * 3;   // random gather, L2-resident
        float px = __ldg(pn + 0);
        float py = __ldg(pn + 1);
        float pz = __ldg(pn + 2);
        // offset = cell_offsets @ cell  (out_e = sum_d co_d * C[d][e])
        float ox = fmaf(cox[i], c00, fmaf(coy[i], c10, coz[i] * c20));
        float oy = fmaf(cox[i], c01, fmaf(coy[i], c11, coz[i] * c21));
        float oz = fmaf(cox[i], c02, fmaf(coy[i], c12, coz[i] * c22));
        float dx = px - ax + ox;
        float dy = py - ay + oy;
        float dz = pz - az + oz;
        float d  = sqrtf(fmaf(dx, dx, fmaf(dy, dy, dz * dz)));
        res[i] = mm[i] ? d : 0.0f;
    }

    *reinterpret_cast<float4*>(out + base) = make_float4(res[0], res[1], res[2], res[3]);
}

extern "C" void kernel_launch(void* const* d_in, const int* in_sizes, int n_in,
                              void* d_out, int out_size)
{
    const float* pos  = (const float*)d_in[0];   // (B,A,3)
    const int*   nbr  = (const int*)d_in[1];     // (B,A,N) int32
    const float* cell = (const float*)d_in[2];   // (B,3,3)
    const float* coff = (const float*)d_in[3];   // (B,A,N,3)
    const int*   mask = (const int*)d_in[4];     // (B,A,N) int32

    // derive shapes: in_sizes[2] = B*9, in_sizes[0] = B*A*3, in_sizes[1] = B*A*N
    int B = in_sizes[2] / 9;
    int A = in_sizes[0] / (3 * B);
    int N = in_sizes[1] / (B * A);

    long long total    = (long long)B * A * N;
    long long n_groups = total >> 2;   // 4 neighbors per thread

    int threads = 256;
    long long blocks = (n_groups + threads - 1) / threads;

    atom_distances_kernel<<<(unsigned)blocks, threads>>>(
        pos, nbr, cell, coff, mask, (float*)d_out, A, N, n_groups);
}

// round 7
// speedup vs baseline: 1.3268x; 1.3268x over previous
#include <cuda_runtime.h>
#include <cstdint>

// AtomDistances: out[b,a,n] = mask ? || pos[nbr[b,a,n]] - pos[b,a] + cell_offsets[b,a,n,:] @ cell[b] || : 0
// B=16, A=4096, N=128. dtypes (harness cast): neighbors int32, mask int32.
//
// R6: L1tex-wavefront bottleneck (L1=65%, DRAM=48% in R5) removed by staging the
// batch's positions (48 KB) in shared memory. The random gather becomes LDS with
// stride-3 addressing (coprime with 32 banks -> ~4-way conflicts) instead of
// ~300 L1 wavefronts/warp of scalar LDGs.
//
// Grid = 37 x 16 = 592 blocks = one full wave at 4 blocks/SM (48 KB smem each).
// Each block stages positions once, then loops over its chunk of neighbor groups.
// Streaming accesses stay fully vectorized (int4 / 3xfloat4 / int4 / float4).

#define THREADS 256

__global__ void __launch_bounds__(THREADS) atom_distances_kernel(
    const float* __restrict__ pos,    // (B, A, 3)
    const int*   __restrict__ nbr,    // (B, A, N) int32
    const float* __restrict__ cell,   // (B, 3, 3)
    const float* __restrict__ coff,   // (B, A, N, 3)
    const int*   __restrict__ mask,   // (B, A, N) int32 (0/1)
    float*       __restrict__ out,    // (B, A, N)
    int A, int N)
{
    __shared__ float4 s_pos4[3072];                  // 48 KB = A*3 floats
    float* s_pos = reinterpret_cast<float*>(s_pos4);

    const int b   = blockIdx.y;
    const int tid = threadIdx.x;

    // ---- stage this batch's positions into smem (float4-aligned: A*3*4 B % 16 == 0)
    const float4* pb4 = reinterpret_cast<const float4*>(pos + (size_t)b * A * 3);
    const int n_vec4 = (A * 3) / 4;                  // 3072
#pragma unroll 4
    for (int i = tid; i < n_vec4; i += THREADS)
        s_pos4[i] = pb4[i];

    // ---- cell matrix for this batch, hoisted (L1-resident)
    const float* C = cell + (size_t)b * 9;
    float c00 = __ldg(C+0), c01 = __ldg(C+1), c02 = __ldg(C+2);
    float c10 = __ldg(C+3), c11 = __ldg(C+4), c12 = __ldg(C+5);
    float c20 = __ldg(C+6), c21 = __ldg(C+7), c22 = __ldg(C+8);

    __syncthreads();

    const int ng_per_atom     = N >> 2;              // 32 groups of 4 per atom
    const int groups_per_batch = A * ng_per_atom;    // 131072
    const int chunk = (groups_per_batch + gridDim.x - 1) / gridDim.x;
    const int start = blockIdx.x * chunk;
    const int end   = min(start + chunk, groups_per_batch);

    const long long bbase = (long long)b * A * N;

    for (int gl = start + tid; gl < end; gl += THREADS) {
        int a  = gl / ng_per_atom;
        int n4 = gl - a * ng_per_atom;
        long long base = bbase + (long long)a * N + n4 * 4;

        // --- front-batched wide streaming loads ---
        int4 nb4 = *reinterpret_cast<const int4*>(nbr + base);
        const float4* co4 = reinterpret_cast<const float4*>(coff + base * 3);
        float4 q0 = co4[0];
        float4 q1 = co4[1];
        float4 q2 = co4[2];
        int4 m4 = *reinterpret_cast<const int4*>(mask + base);

        // central atom position from smem (broadcast across the 8 threads/atom)
        float ax = s_pos[a*3 + 0], ay = s_pos[a*3 + 1], az = s_pos[a*3 + 2];

        int ni[4] = { nb4.x, nb4.y, nb4.z, nb4.w };
#pragma unroll
        for (int i = 0; i < 4; i++)                  // defensive clamp
            ni[i] = min(max(ni[i], 0), A - 1);

        float cox[4] = { q0.x, q0.w, q1.z, q2.y };
        float coy[4] = { q0.y, q1.x, q1.w, q2.z };
        float coz[4] = { q0.z, q1.y, q2.x, q2.w };
        int   mm[4]  = { m4.x, m4.y, m4.z, m4.w };

        float res[4];
#pragma unroll
        for (int i = 0; i < 4; i++) {
            int p = ni[i] * 3;                       // stride 3: coprime w/ 32 banks
            float px = s_pos[p + 0];
            float py = s_pos[p + 1];
            float pz = s_pos[p + 2];
            float ox = fmaf(cox[i], c00, fmaf(coy[i], c10, coz[i] * c20));
            float oy = fmaf(cox[i], c01, fmaf(coy[i], c11, coz[i] * c21));
            float oz = fmaf(cox[i], c02, fmaf(coy[i], c12, coz[i] * c22));
            float dx = px - ax + ox;
            float dy = py - ay + oy;
            float dz = pz - az + oz;
            float d  = sqrtf(fmaf(dx, dx, fmaf(dy, dy, dz * dz)));
            res[i] = mm[i] ? d : 0.0f;
        }

        *reinterpret_cast<float4*>(out + base) =
            make_float4(res[0], res[1], res[2], res[3]);
    }
}

extern "C" void kernel_launch(void* const* d_in, const int* in_sizes, int n_in,
                              void* d_out, int out_size)
{
    const float* pos  = (const float*)d_in[0];   // (B,A,3)
    const int*   nbr  = (const int*)d_in[1];     // (B,A,N) int32
    const float* cell = (const float*)d_in[2];   // (B,3,3)
    const float* coff = (const float*)d_in[3];   // (B,A,N,3)
    const int*   mask = (const int*)d_in[4];     // (B,A,N) int32

    int B = in_sizes[2] / 9;
    int A = in_sizes[0] / (3 * B);
    int N = in_sizes[1] / (B * A);

    // 37 x 16 = 592 blocks = 148 SMs x 4 blocks (48 KB smem each): one full wave.
    dim3 grid(37, B, 1);
    atom_distances_kernel<<<grid, THREADS>>>(
        pos, nbr, cell, coff, mask, (float*)d_out, A, N);
}